// round 16
// baseline (speedup 1.0000x reference)
#include <cuda_runtime.h>
#include <cuda_fp16.h>
#include <math.h>

#define BATCH   16384
#define HD      256
#define SAMPLES 16
#define MROWS   128
#define NLAYER  3
#define TOTCH   12          // 3 layers x 4 chunks of K=64
#define NTHREADS 1024

typedef unsigned int u32;

// ---------------- global scratch: W^T rounded to fp16
__device__ __align__(16) __half g_Whi[NLAYER * HD * HD];

__global__ void prep_split(const float* __restrict__ W1,
                           const float* __restrict__ W2,
                           const float* __restrict__ W3) {
    int b = blockIdx.x;               // 0..767
    int layer = b >> 8, n = b & 255, k = threadIdx.x;
    const float* W = layer == 0 ? W1 : (layer == 1 ? W2 : W3);
    g_Whi[(layer * HD + n) * HD + k] = __float2half_rn(W[k * HD + n]);
}

// ---------------- smem layout (bytes)
#define SROW    528          // 256 halfs + 16B pad (33 segs, coprime 8)
#define WROW    144          // 64 halfs + 16B pad  (9 segs, coprime 8)
#define SM_S    0            // 128*528 = 67584
#define SM_WB   67584        // 3 bufs x 256*144 = 110592 -> 178176
#define WB_BUF  36864
#define SM_BIAS 178176       // 3*1024 -> 181248
#define SM_WO   181248       // 2048   -> 183296
#define SM_OUT  183296       // 8 groups x 128 rows x 2 = 8192 -> 191488
#define SM_TOT  191488

__device__ __forceinline__ u32 s2u(const void* p) { return (u32)__cvta_generic_to_shared(p); }

__device__ __forceinline__ void cpasync16(u32 dst, const void* src) {
    asm volatile("cp.async.cg.shared.global [%0], [%1], 16;" :: "r"(dst), "l"(src));
}
__device__ __forceinline__ void ldsm4(u32* d, u32 addr) {
    asm volatile("ldmatrix.sync.aligned.m8n8.x4.shared.b16 {%0,%1,%2,%3}, [%4];"
                 : "=r"(d[0]), "=r"(d[1]), "=r"(d[2]), "=r"(d[3]) : "r"(addr));
}
__device__ __forceinline__ void mma16816(float* c, const u32* a, u32 b0, u32 b1) {
    asm volatile("mma.sync.aligned.m16n8k16.row.col.f32.f16.f16.f32 "
                 "{%0,%1,%2,%3},{%4,%5,%6,%7},{%8,%9},{%0,%1,%2,%3};"
                 : "+f"(c[0]), "+f"(c[1]), "+f"(c[2]), "+f"(c[3])
                 : "r"(a[0]), "r"(a[1]), "r"(a[2]), "r"(a[3]), "r"(b0), "r"(b1));
}
__device__ __forceinline__ float ftanh(float u) {
    float a = fabsf(u);
    float t = __expf(-2.f * a);
    float h = __fdividef(1.f - t, 1.f + t);
    return copysignf(h, u);
}
// fp16 store at (row, k) (k even, 2 values)
__device__ __forceinline__ void store_h(char* smem, int row, int k,
                                        float vx, float vy) {
    __half2 hp = __halves2half2(__float2half_rn(vx), __float2half_rn(vy));
    *(u32*)(smem + SM_S + row * SROW + k * 2) = *(u32*)&hp;
}

// one K=64 chunk of W^T: 256 rows x 8 x 16B = 2048 transfers; 1024 thr x2.
__device__ __forceinline__ void load_chunk(char* smem, int cg, int tid) {
    const int layer = cg >> 2, c = cg & 3, bsel = cg % 3;
    const __half* sh = g_Whi + layer * (HD * HD) + c * 64;
    const u32 dH = s2u(smem + SM_WB) + (u32)(bsel * WB_BUF);
#pragma unroll
    for (int t = 0; t < 2; t++) {
        const int i = tid + t * 1024;
        const int n = i >> 3, s = i & 7;
        cpasync16(dH + (u32)(n * WROW + s * 16), sh + n * HD + s * 8);
    }
    asm volatile("cp.async.commit_group;");
}

__global__ __launch_bounds__(NTHREADS, 1)
void grad_kernel(const float* __restrict__ x,
                 const float* __restrict__ W0, const float* __restrict__ b0,
                 const float* __restrict__ b1, const float* __restrict__ b2,
                 const float* __restrict__ b3,
                 const float* __restrict__ Wo, const float* __restrict__ bo,
                 float* __restrict__ out) {
    extern __shared__ __align__(16) char smem[];
    const int tid  = threadIdx.x;
    const int wid  = tid >> 5;
    const int lane = tid & 31;
    const int wm = wid & 3, wn = wid >> 2;       // 4 m-warps x 8 n-warps
    const int m0 = wm * 32, nb0 = wn * 32;       // warp tile 32x32
    const int s0 = blockIdx.x * SAMPLES;

    // ---- stage bias + Wo
    if (tid < HD) {
        ((float*)(smem + SM_BIAS))[tid]        = b1[tid];
        ((float*)(smem + SM_BIAS + 1024))[tid] = b2[tid];
        ((float*)(smem + SM_BIAS + 2048))[tid] = b3[tid];
    }
    if (tid < 512) ((float*)(smem + SM_WO))[tid] = Wo[tid];

    // ---- prologue: prefetch chunks 0,1 (overlaps layer 0)
    load_chunk(smem, 0, tid);
    load_chunk(smem, 1, tid);

    // ---- layer 0: 4 -> 256 jet, write fp16 S (64 threads per sample)
    {
        const int samp = tid >> 6, kg = tid & 63;
        const float4 xv = __ldg((const float4*)x + (s0 + samp));
#pragma unroll
        for (int jp = 0; jp < 2; jp++) {
            const int k = kg * 4 + jp * 2;
            float vv[2][8];
#pragma unroll
            for (int e = 0; e < 2; e++) {
                const int ke = k + e;
                float w0 = __ldg(W0 + 0 * HD + ke), w1 = __ldg(W0 + 1 * HD + ke);
                float w2 = __ldg(W0 + 2 * HD + ke), w3 = __ldg(W0 + 3 * HD + ke);
                float u0 = __ldg(b0 + ke) + xv.x * w0 + xv.y * w1 + xv.z * w2 + xv.w * w3;
                float h = ftanh(u0), d = 1.f - h * h;
                vv[e][0] = h;
                vv[e][1] = d * w0; vv[e][2] = d * w1; vv[e][3] = d * w2; vv[e][4] = d * w3;
                float c2 = -2.f * h * d;
                vv[e][5] = c2 * w0 * w0; vv[e][6] = c2 * w1 * w1; vv[e][7] = c2 * w2 * w2;
            }
#pragma unroll
            for (int ch = 0; ch < 8; ch++)
                store_h(smem, samp * 8 + ch, k, vv[0][ch], vv[1][ch]);
        }
    }

    // ---- lane bases for ldmatrix
    const int lt = lane >> 3, lr = lane & 7;
    const u32 aS = s2u(smem + SM_S)
                 + (u32)((m0 + ((lt & 1) << 3) + lr) * SROW + ((lt >> 1) << 4));
    const u32 bOff = (u32)((nb0 + ((lt >> 1) << 3) + lr) * WROW + ((lt & 1) << 4));
    const int q = lane & 3, ch = lane >> 2;
    const int srcl = (ch >= 5) ? (((ch - 4) << 2) + q) : lane;

    float acc[2][4][4];    // [m-tile][n8][frag]

    for (int L = 0; L < NLAYER; L++) {
#pragma unroll
        for (int mt = 0; mt < 2; mt++)
#pragma unroll
            for (int nt = 0; nt < 4; nt++)
#pragma unroll
                for (int j = 0; j < 4; j++) acc[mt][nt][j] = 0.f;

        for (int c = 0; c < 4; c++) {
            const int cg = L * 4 + c;
            if (cg + 1 < TOTCH) asm volatile("cp.async.wait_group 1;");
            else                asm volatile("cp.async.wait_group 0;");
            __syncthreads();   // chunk cg visible; all warps done with cg-1
            if (cg + 2 < TOTCH) load_chunk(smem, cg + 2, tid);  // buf (cg-1)%3

            const u32 wb = s2u(smem + SM_WB) + (u32)((cg % 3) * WB_BUF) + bOff;
#pragma unroll
            for (int kt = 0; kt < 4; kt++) {
                const u32 ka = (u32)(c * 128 + kt * 32);
                const u32 wk = wb + (u32)(kt * 32);
                u32 A[2][4], B[2][4];
                ldsm4(A[0], aS + ka);
                ldsm4(A[1], aS + 16 * SROW + ka);
                ldsm4(B[0], wk);
                ldsm4(B[1], wk + 16 * WROW);
                // 8 independent MMAs on distinct accumulators
#pragma unroll
                for (int np = 0; np < 2; np++)
#pragma unroll
                    for (int mt = 0; mt < 2; mt++) {
                        mma16816(acc[mt][2 * np],     A[mt], B[np][0], B[np][1]);
                        mma16816(acc[mt][2 * np + 1], A[mt], B[np][2], B[np][3]);
                    }
            }
        }
        __syncthreads();   // all A-frag reads of S done before epilogue writes

        // ---- epilogue: tanh-jet; h computed ONCE on ch==0 lanes, broadcast
        const float* bs = (const float*)(smem + SM_BIAS) + L * HD;
        if (L < NLAYER - 1) {
#pragma unroll
            for (int mt = 0; mt < 2; mt++)
#pragma unroll
                for (int nt = 0; nt < 4; nt++) {
                    const int n = nb0 + nt * 8 + 2 * q;
                    const float2 bn = *(const float2*)(bs + n);
#pragma unroll
                    for (int sh = 0; sh < 2; sh++) {
                        float ux = acc[mt][nt][sh * 2 + 0], uy = acc[mt][nt][sh * 2 + 1];
                        // ch==0 lanes own u0; compute h locally, others get it
                        float hsrcx = (ch == 0) ? ftanh(ux + bn.x) : 0.f;
                        float hsrcy = (ch == 0) ? ftanh(uy + bn.y) : 0.f;
                        float hx = __shfl_sync(0xffffffffu, hsrcx, q);
                        float hy = __shfl_sync(0xffffffffu, hsrcy, q);
                        float u1x = __shfl_sync(0xffffffffu, ux, srcl);
                        float u1y = __shfl_sync(0xffffffffu, uy, srcl);
                        float dx = 1.f - hx * hx, dy = 1.f - hy * hy;
                        float vx, vy;
                        if (ch == 0)      { vx = hx; vy = hy; }
                        else if (ch < 5)  { vx = dx * ux; vy = dy * uy; }
                        else {
                            vx = dx * (ux - 2.f * hx * u1x * u1x);
                            vy = dy * (uy - 2.f * hy * u1y * u1y);
                        }
                        store_h(smem, m0 + mt * 16 + sh * 8 + ch, n, vx, vy);
                    }
                }
            __syncthreads();
        } else {
            // ---- fused output head: partial S.Wo from registers
            const float* wos = (const float*)(smem + SM_WO);
            float o[2][2][2] = {};   // [mt][sh][dout]
#pragma unroll
            for (int mt = 0; mt < 2; mt++)
#pragma unroll
                for (int nt = 0; nt < 4; nt++) {
                    const int n = nb0 + nt * 8 + 2 * q;
                    const float2 bn = *(const float2*)(bs + n);
                    const float2 w0 = *(const float2*)(wos + n * 2);
                    const float2 w1 = *(const float2*)(wos + n * 2 + 2);
#pragma unroll
                    for (int sh = 0; sh < 2; sh++) {
                        float ux = acc[mt][nt][sh * 2 + 0], uy = acc[mt][nt][sh * 2 + 1];
                        float hsrcx = (ch == 0) ? ftanh(ux + bn.x) : 0.f;
                        float hsrcy = (ch == 0) ? ftanh(uy + bn.y) : 0.f;
                        float hx = __shfl_sync(0xffffffffu, hsrcx, q);
                        float hy = __shfl_sync(0xffffffffu, hsrcy, q);
                        float u1x = __shfl_sync(0xffffffffu, ux, srcl);
                        float u1y = __shfl_sync(0xffffffffu, uy, srcl);
                        float dx = 1.f - hx * hx, dy = 1.f - hy * hy;
                        float vx, vy;
                        if (ch == 0)      { vx = hx; vy = hy; }
                        else if (ch < 5)  { vx = dx * ux; vy = dy * uy; }
                        else {
                            vx = dx * (ux - 2.f * hx * u1x * u1x);
                            vy = dy * (uy - 2.f * hy * u1y * u1y);
                        }
                        o[mt][sh][0] += vx * w0.x + vy * w1.x;
                        o[mt][sh][1] += vx * w0.y + vy * w1.y;
                    }
                }
            // quad-reduce over the 4 n-lanes of this (row, channel)
#pragma unroll
            for (int mt = 0; mt < 2; mt++)
#pragma unroll
                for (int sh = 0; sh < 2; sh++)
#pragma unroll
                    for (int d = 0; d < 2; d++) {
                        o[mt][sh][d] += __shfl_xor_sync(0xffffffffu, o[mt][sh][d], 1);
                        o[mt][sh][d] += __shfl_xor_sync(0xffffffffu, o[mt][sh][d], 2);
                    }
            if (q == 0) {
                float* ob2 = (float*)(smem + SM_OUT);   // [group][row][d]
#pragma unroll
                for (int mt = 0; mt < 2; mt++)
#pragma unroll
                    for (int sh = 0; sh < 2; sh++) {
                        const int r = m0 + mt * 16 + sh * 8 + ch;
                        ob2[(wn * 128 + r) * 2 + 0] = o[mt][sh][0];
                        ob2[(wn * 128 + r) * 2 + 1] = o[mt][sh][1];
                    }
            }
            __syncthreads();
        }
    }

    // ---- per-sample combine + stores (fixed-order group sum: deterministic)
    if (tid < SAMPLES) {
        const float* ob2 = (const float*)(smem + SM_OUT);
        float obv[16];
#pragma unroll
        for (int i = 0; i < 16; i++) {
            const int m = tid * 8 + (i >> 1), d = i & 1;
            float s01 = ob2[(0 * 128 + m) * 2 + d] + ob2[(1 * 128 + m) * 2 + d];
            float s23 = ob2[(2 * 128 + m) * 2 + d] + ob2[(3 * 128 + m) * 2 + d];
            float s45 = ob2[(4 * 128 + m) * 2 + d] + ob2[(5 * 128 + m) * 2 + d];
            float s67 = ob2[(6 * 128 + m) * 2 + d] + ob2[(7 * 128 + m) * 2 + d];
            obv[i] = (s01 + s23) + (s45 + s67);
        }
        float c  = obv[0] + __ldg(bo);
        float Fi = obv[1] + __ldg(bo + 1);
        float cj[4], Fj[4];
#pragma unroll
        for (int i = 0; i < 4; i++) { cj[i] = obv[(1 + i) * 2]; Fj[i] = obv[(1 + i) * 2 + 1]; }
        float trHc = 0.f, FiLap = 0.f;
#pragma unroll
        for (int i = 0; i < 3; i++) { trHc += obv[(5 + i) * 2]; FiLap += obv[(5 + i) * 2 + 1]; }
        float dotg = cj[0] * Fj[0] + cj[1] * Fj[1] + cj[2] * Fj[2];
        float sumg = cj[0] + cj[1] + cj[2];
        float jdiv = -trHc - (dotg + c * FiLap) + 0.1f * sumg;

        const int idx = s0 + tid;
        out[idx]                     = c;
        out[BATCH + idx]             = cj[3];
        out[2 * BATCH + idx * 3 + 0] = cj[0];
        out[2 * BATCH + idx * 3 + 1] = cj[1];
        out[2 * BATCH + idx * 3 + 2] = cj[2];
        out[5 * BATCH + idx]         = Fi;
        out[6 * BATCH + idx * 3 + 0] = Fj[0];
        out[6 * BATCH + idx * 3 + 1] = Fj[1];
        out[6 * BATCH + idx * 3 + 2] = Fj[2];
        out[9 * BATCH + idx]         = FiLap;
        out[10 * BATCH + idx]        = jdiv;
    }
}

extern "C" void kernel_launch(void* const* d_in, const int* in_sizes, int n_in,
                              void* d_out, int out_size) {
    const float* x  = (const float*)d_in[0];
    const float* W0 = (const float*)d_in[1];
    const float* b0 = (const float*)d_in[2];
    const float* W1 = (const float*)d_in[3];
    const float* b1 = (const float*)d_in[4];
    const float* W2 = (const float*)d_in[5];
    const float* b2 = (const float*)d_in[6];
    const float* W3 = (const float*)d_in[7];
    const float* b3 = (const float*)d_in[8];
    const float* Wo = (const float*)d_in[9];
    const float* bo = (const float*)d_in[10];

    prep_split<<<NLAYER * HD, HD>>>(W1, W2, W3);

    cudaFuncSetAttribute(grad_kernel, cudaFuncAttributeMaxDynamicSharedMemorySize, SM_TOT);
    grad_kernel<<<BATCH / SAMPLES, NTHREADS, SM_TOT>>>(x, W0, b0, b1, b2, b3,
                                                       Wo, bo, (float*)d_out);
}

// round 17
// speedup vs baseline: 1.0554x; 1.0554x over previous
#include <cuda_runtime.h>
#include <cuda_fp16.h>
#include <math.h>

#define BATCH   16384
#define HD      256
#define SAMPLES 16
#define MROWS   128
#define NLAYER  3
#define TOTCH   6           // 3 layers x 2 chunks of K=128
#define NTHREADS 1024

typedef unsigned int u32;

// ---------------- global scratch: W^T rounded to fp16
__device__ __align__(16) __half g_Whi[NLAYER * HD * HD];

__global__ void prep_split(const float* __restrict__ W1,
                           const float* __restrict__ W2,
                           const float* __restrict__ W3) {
    int b = blockIdx.x;               // 0..767
    int layer = b >> 8, n = b & 255, k = threadIdx.x;
    const float* W = layer == 0 ? W1 : (layer == 1 ? W2 : W3);
    g_Whi[(layer * HD + n) * HD + k] = __float2half_rn(W[k * HD + n]);
}

// ---------------- smem layout (bytes)
#define SROW    528          // 256 halfs + 16B pad (33 segs, coprime 8)
#define WROW    272          // 128 halfs + 16B pad (17 segs, coprime 8)
#define SM_S    0            // 128*528 = 67584
#define SM_WB   67584        // 2 bufs x 256*272 = 139264 -> 206848
#define WB_BUF  69632
#define SM_BIAS 206848       // 3*1024 -> 209920
#define SM_WO   209920       // 2048   -> 211968
#define SM_OUT  211968       // 8 groups x 128 rows x 2 = 8192 -> 220160
#define SM_TOT  220160

__device__ __forceinline__ u32 s2u(const void* p) { return (u32)__cvta_generic_to_shared(p); }

__device__ __forceinline__ void cpasync16(u32 dst, const void* src) {
    asm volatile("cp.async.cg.shared.global [%0], [%1], 16;" :: "r"(dst), "l"(src));
}
__device__ __forceinline__ void ldsm4(u32* d, u32 addr) {
    asm volatile("ldmatrix.sync.aligned.m8n8.x4.shared.b16 {%0,%1,%2,%3}, [%4];"
                 : "=r"(d[0]), "=r"(d[1]), "=r"(d[2]), "=r"(d[3]) : "r"(addr));
}
__device__ __forceinline__ void mma16816(float* c, const u32* a, u32 b0, u32 b1) {
    asm volatile("mma.sync.aligned.m16n8k16.row.col.f32.f16.f16.f32 "
                 "{%0,%1,%2,%3},{%4,%5,%6,%7},{%8,%9},{%0,%1,%2,%3};"
                 : "+f"(c[0]), "+f"(c[1]), "+f"(c[2]), "+f"(c[3])
                 : "r"(a[0]), "r"(a[1]), "r"(a[2]), "r"(a[3]), "r"(b0), "r"(b1));
}
__device__ __forceinline__ float ftanh(float u) {
    float a = fabsf(u);
    float t = __expf(-2.f * a);
    float h = __fdividef(1.f - t, 1.f + t);
    return copysignf(h, u);
}
// fp16 store at (row, k) (k even, 2 values)
__device__ __forceinline__ void store_h(char* smem, int row, int k,
                                        float vx, float vy) {
    __half2 hp = __halves2half2(__float2half_rn(vx), __float2half_rn(vy));
    *(u32*)(smem + SM_S + row * SROW + k * 2) = *(u32*)&hp;
}

// one K=128 chunk of W^T: 256 rows x 16 x 16B = 4096 transfers; 1024 thr x4.
__device__ __forceinline__ void load_chunk(char* smem, int cg, int tid) {
    const int layer = cg >> 1, c = cg & 1, bsel = cg & 1;
    const __half* sh = g_Whi + layer * (HD * HD) + c * 128;
    const u32 dH = s2u(smem + SM_WB) + (u32)(bsel * WB_BUF);
#pragma unroll
    for (int t = 0; t < 4; t++) {
        const int i = tid + t * 1024;
        const int n = i >> 4, s = i & 15;
        cpasync16(dH + (u32)(n * WROW + s * 16), sh + n * HD + s * 8);
    }
    asm volatile("cp.async.commit_group;");
}

__global__ __launch_bounds__(NTHREADS, 1)
void grad_kernel(const float* __restrict__ x,
                 const float* __restrict__ W0, const float* __restrict__ b0,
                 const float* __restrict__ b1, const float* __restrict__ b2,
                 const float* __restrict__ b3,
                 const float* __restrict__ Wo, const float* __restrict__ bo,
                 float* __restrict__ out) {
    extern __shared__ __align__(16) char smem[];
    const int tid  = threadIdx.x;
    const int wid  = tid >> 5;
    const int lane = tid & 31;
    const int wm = wid & 3, wn = wid >> 2;       // 4 m-warps x 8 n-warps
    const int m0 = wm * 32, nb0 = wn * 32;       // warp tile 32x32
    const int s0 = blockIdx.x * SAMPLES;

    // ---- stage bias + Wo
    if (tid < HD) {
        ((float*)(smem + SM_BIAS))[tid]        = b1[tid];
        ((float*)(smem + SM_BIAS + 1024))[tid] = b2[tid];
        ((float*)(smem + SM_BIAS + 2048))[tid] = b3[tid];
    }
    if (tid < 512) ((float*)(smem + SM_WO))[tid] = Wo[tid];

    // ---- prologue: prefetch chunk 0 (overlaps layer 0)
    load_chunk(smem, 0, tid);

    // ---- layer 0: 4 -> 256 jet, write fp16 S (64 threads per sample)
    {
        const int samp = tid >> 6, kg = tid & 63;
        const float4 xv = __ldg((const float4*)x + (s0 + samp));
#pragma unroll
        for (int jp = 0; jp < 2; jp++) {
            const int k = kg * 4 + jp * 2;
            float vv[2][8];
#pragma unroll
            for (int e = 0; e < 2; e++) {
                const int ke = k + e;
                float w0 = __ldg(W0 + 0 * HD + ke), w1 = __ldg(W0 + 1 * HD + ke);
                float w2 = __ldg(W0 + 2 * HD + ke), w3 = __ldg(W0 + 3 * HD + ke);
                float u0 = __ldg(b0 + ke) + xv.x * w0 + xv.y * w1 + xv.z * w2 + xv.w * w3;
                float h = ftanh(u0), d = 1.f - h * h;
                vv[e][0] = h;
                vv[e][1] = d * w0; vv[e][2] = d * w1; vv[e][3] = d * w2; vv[e][4] = d * w3;
                float c2 = -2.f * h * d;
                vv[e][5] = c2 * w0 * w0; vv[e][6] = c2 * w1 * w1; vv[e][7] = c2 * w2 * w2;
            }
#pragma unroll
            for (int ch = 0; ch < 8; ch++)
                store_h(smem, samp * 8 + ch, k, vv[0][ch], vv[1][ch]);
        }
    }

    // ---- lane bases for ldmatrix
    const int lt = lane >> 3, lr = lane & 7;
    const u32 aS = s2u(smem + SM_S)
                 + (u32)((m0 + ((lt & 1) << 3) + lr) * SROW + ((lt >> 1) << 4));
    const u32 bOff = (u32)((nb0 + ((lt >> 1) << 3) + lr) * WROW + ((lt & 1) << 4));
    const int q = lane & 3, ch = lane >> 2;
    const int srcl = (ch >= 5) ? (((ch - 4) << 2) + q) : lane;

    float acc[2][4][4];    // [m-tile][n8][frag]

    for (int L = 0; L < NLAYER; L++) {
#pragma unroll
        for (int mt = 0; mt < 2; mt++)
#pragma unroll
            for (int nt = 0; nt < 4; nt++)
#pragma unroll
                for (int j = 0; j < 4; j++) acc[mt][nt][j] = 0.f;

        for (int c = 0; c < 2; c++) {
            const int cg = L * 2 + c;
            asm volatile("cp.async.wait_group 0;");   // chunk cg landed
            __syncthreads();   // + all warps done with buffer of chunk cg-1
            if (cg + 1 < TOTCH) load_chunk(smem, cg + 1, tid);  // other buffer

            const u32 wb = s2u(smem + SM_WB) + (u32)((cg & 1) * WB_BUF) + bOff;
#pragma unroll
            for (int kt = 0; kt < 8; kt++) {
                const u32 ka = (u32)(c * 256 + kt * 32);
                const u32 wk = wb + (u32)(kt * 32);
                u32 A[2][4], B[2][4];
                ldsm4(A[0], aS + ka);
                ldsm4(A[1], aS + 16 * SROW + ka);
                ldsm4(B[0], wk);
                ldsm4(B[1], wk + 16 * WROW);
                // 8 independent MMAs on distinct accumulators
#pragma unroll
                for (int np = 0; np < 2; np++)
#pragma unroll
                    for (int mt = 0; mt < 2; mt++) {
                        mma16816(acc[mt][2 * np],     A[mt], B[np][0], B[np][1]);
                        mma16816(acc[mt][2 * np + 1], A[mt], B[np][2], B[np][3]);
                    }
            }
        }
        __syncthreads();   // all A-frag reads of S done before epilogue writes

        // ---- epilogue: tanh-jet in registers
        const float* bs = (const float*)(smem + SM_BIAS) + L * HD;
        if (L < NLAYER - 1) {
#pragma unroll
            for (int mt = 0; mt < 2; mt++)
#pragma unroll
                for (int nt = 0; nt < 4; nt++) {
                    const int n = nb0 + nt * 8 + 2 * q;
                    const float2 bn = *(const float2*)(bs + n);
#pragma unroll
                    for (int sh = 0; sh < 2; sh++) {
                        float ux = acc[mt][nt][sh * 2 + 0], uy = acc[mt][nt][sh * 2 + 1];
                        float u0x = __shfl_sync(0xffffffffu, ux, q);
                        float u0y = __shfl_sync(0xffffffffu, uy, q);
                        float u1x = __shfl_sync(0xffffffffu, ux, srcl);
                        float u1y = __shfl_sync(0xffffffffu, uy, srcl);
                        float hx = ftanh(u0x + bn.x), hy = ftanh(u0y + bn.y);
                        float dx = 1.f - hx * hx, dy = 1.f - hy * hy;
                        float vx, vy;
                        if (ch == 0)      { vx = hx; vy = hy; }
                        else if (ch < 5)  { vx = dx * ux; vy = dy * uy; }
                        else {
                            vx = dx * (ux - 2.f * hx * u1x * u1x);
                            vy = dy * (uy - 2.f * hy * u1y * u1y);
                        }
                        store_h(smem, m0 + mt * 16 + sh * 8 + ch, n, vx, vy);
                    }
                }
            __syncthreads();
        } else {
            // ---- fused output head: partial S.Wo from registers
            const float* wos = (const float*)(smem + SM_WO);
            float o[2][2][2] = {};   // [mt][sh][dout]
#pragma unroll
            for (int mt = 0; mt < 2; mt++)
#pragma unroll
                for (int nt = 0; nt < 4; nt++) {
                    const int n = nb0 + nt * 8 + 2 * q;
                    const float2 bn = *(const float2*)(bs + n);
                    const float2 w0 = *(const float2*)(wos + n * 2);
                    const float2 w1 = *(const float2*)(wos + n * 2 + 2);
#pragma unroll
                    for (int sh = 0; sh < 2; sh++) {
                        float ux = acc[mt][nt][sh * 2 + 0], uy = acc[mt][nt][sh * 2 + 1];
                        float u0x = __shfl_sync(0xffffffffu, ux, q);
                        float u0y = __shfl_sync(0xffffffffu, uy, q);
                        float u1x = __shfl_sync(0xffffffffu, ux, srcl);
                        float u1y = __shfl_sync(0xffffffffu, uy, srcl);
                        float hx = ftanh(u0x + bn.x), hy = ftanh(u0y + bn.y);
                        float dx = 1.f - hx * hx, dy = 1.f - hy * hy;
                        float vx, vy;
                        if (ch == 0)      { vx = hx; vy = hy; }
                        else if (ch < 5)  { vx = dx * ux; vy = dy * uy; }
                        else {
                            vx = dx * (ux - 2.f * hx * u1x * u1x);
                            vy = dy * (uy - 2.f * hy * u1y * u1y);
                        }
                        o[mt][sh][0] += vx * w0.x + vy * w1.x;
                        o[mt][sh][1] += vx * w0.y + vy * w1.y;
                    }
                }
            // quad-reduce over the 4 n-lanes of this (row, channel)
#pragma unroll
            for (int mt = 0; mt < 2; mt++)
#pragma unroll
                for (int sh = 0; sh < 2; sh++)
#pragma unroll
                    for (int d = 0; d < 2; d++) {
                        o[mt][sh][d] += __shfl_xor_sync(0xffffffffu, o[mt][sh][d], 1);
                        o[mt][sh][d] += __shfl_xor_sync(0xffffffffu, o[mt][sh][d], 2);
                    }
            if (q == 0) {
                float* ob2 = (float*)(smem + SM_OUT);   // [group][row][d]
#pragma unroll
                for (int mt = 0; mt < 2; mt++)
#pragma unroll
                    for (int sh = 0; sh < 2; sh++) {
                        const int r = m0 + mt * 16 + sh * 8 + ch;
                        ob2[(wn * 128 + r) * 2 + 0] = o[mt][sh][0];
                        ob2[(wn * 128 + r) * 2 + 1] = o[mt][sh][1];
                    }
            }
            __syncthreads();
        }
    }

    // ---- per-sample combine + stores (fixed-order group sum: deterministic)
    if (tid < SAMPLES) {
        const float* ob2 = (const float*)(smem + SM_OUT);
        float obv[16];
#pragma unroll
        for (int i = 0; i < 16; i++) {
            const int m = tid * 8 + (i >> 1), d = i & 1;
            float s01 = ob2[(0 * 128 + m) * 2 + d] + ob2[(1 * 128 + m) * 2 + d];
            float s23 = ob2[(2 * 128 + m) * 2 + d] + ob2[(3 * 128 + m) * 2 + d];
            float s45 = ob2[(4 * 128 + m) * 2 + d] + ob2[(5 * 128 + m) * 2 + d];
            float s67 = ob2[(6 * 128 + m) * 2 + d] + ob2[(7 * 128 + m) * 2 + d];
            obv[i] = (s01 + s23) + (s45 + s67);
        }
        float c  = obv[0] + __ldg(bo);
        float Fi = obv[1] + __ldg(bo + 1);
        float cj[4], Fj[4];
#pragma unroll
        for (int i = 0; i < 4; i++) { cj[i] = obv[(1 + i) * 2]; Fj[i] = obv[(1 + i) * 2 + 1]; }
        float trHc = 0.f, FiLap = 0.f;
#pragma unroll
        for (int i = 0; i < 3; i++) { trHc += obv[(5 + i) * 2]; FiLap += obv[(5 + i) * 2 + 1]; }
        float dotg = cj[0] * Fj[0] + cj[1] * Fj[1] + cj[2] * Fj[2];
        float sumg = cj[0] + cj[1] + cj[2];
        float jdiv = -trHc - (dotg + c * FiLap) + 0.1f * sumg;

        const int idx = s0 + tid;
        out[idx]                     = c;
        out[BATCH + idx]             = cj[3];
        out[2 * BATCH + idx * 3 + 0] = cj[0];
        out[2 * BATCH + idx * 3 + 1] = cj[1];
        out[2 * BATCH + idx * 3 + 2] = cj[2];
        out[5 * BATCH + idx]         = Fi;
        out[6 * BATCH + idx * 3 + 0] = Fj[0];
        out[6 * BATCH + idx * 3 + 1] = Fj[1];
        out[6 * BATCH + idx * 3 + 2] = Fj[2];
        out[9 * BATCH + idx]         = FiLap;
        out[10 * BATCH + idx]        = jdiv;
    }
}

extern "C" void kernel_launch(void* const* d_in, const int* in_sizes, int n_in,
                              void* d_out, int out_size) {
    const float* x  = (const float*)d_in[0];
    const float* W0 = (const float*)d_in[1];
    const float* b0 = (const float*)d_in[2];
    const float* W1 = (const float*)d_in[3];
    const float* b1 = (const float*)d_in[4];
    const float* W2 = (const float*)d_in[5];
    const float* b2 = (const float*)d_in[6];
    const float* W3 = (const float*)d_in[7];
    const float* b3 = (const float*)d_in[8];
    const float* Wo = (const float*)d_in[9];
    const float* bo = (const float*)d_in[10];

    prep_split<<<NLAYER * HD, HD>>>(W1, W2, W3);

    cudaFuncSetAttribute(grad_kernel, cudaFuncAttributeMaxDynamicSharedMemorySize, SM_TOT);
    grad_kernel<<<BATCH / SAMPLES, NTHREADS, SM_TOT>>>(x, W0, b0, b1, b2, b3,
                                                       Wo, bo, (float*)d_out);
}